// round 15
// baseline (speedup 1.0000x reference)
#include <cuda_runtime.h>
#include <cuda_fp16.h>
#include <cstdint>
#include <math.h>

#define NBk 4
#define Bb  8
#define Tt  1024
#define Dd  1024
#define Vv  256
#define Ii  2816
#define NN  (Bb*Tt)      // 8192 tokens
#define EPSf 1e-6f
#define TC  128          // scan chunk length
#define CH  (Tt/TC)      // 8 chunks

#define DDe (Dd*Dd)                    // 1048576
#define IDe (Ii*Dd)                    // 2883584
#define WPB ((size_t)(4*DDe + 3*IDe))  // halves per block prep region

// ---------------- scratch (device globals; no allocation allowed) ------------
__device__ float  g_Y [NN*Dd];
__device__ __half g_YT[NN*Dd];             // fp16 copy of Y (GEMM A operand)
__device__ __half g_Z [(size_t)NN*3*Dd];   // [NN][3D]: ZF | ZC | ZG  (fp16)
__device__ __half g_H [NN*Dd];             // fp16
__device__ __half g_S [NN*Dd];
__device__ float  g_XO[NN*Dd];
__device__ __half g_XS[NN*Dd];             // fp16 scaled copy of XO
__device__ __half g_UU[(size_t)NN*2*Ii];   // fp16
__device__ __half g_GP[(size_t)NN*Ii];
__device__ __half g_WP[(size_t)NBk * WPB]; // per-block prepped weights (fp16)
__device__ __half g_WO[Vv*Dd];             // prepped out_w (fp16)
__device__ float  g_B3s[NBk][3*Dd];        // per-block concatenated f/c/g bias
__device__ float  g_rA[NN];
__device__ float  g_rB[NN];
__device__ float  g_LB[NBk*Dd];
__device__ float  g_SA[Bb*CH*Dd];
__device__ float  g_SB[Bb*CH*Dd];

// ---------------- PTX helpers -------------------------------------------------
__device__ __forceinline__ uint32_t smem_u32(const void* p) {
    uint32_t a;
    asm("{ .reg .u64 t; cvta.to.shared.u64 t, %1; cvt.u32.u64 %0, t; }" : "=r"(a) : "l"(p));
    return a;
}
static __device__ __forceinline__ void cp16(uint32_t saddr, const void* gaddr) {
    asm volatile("cp.async.cg.shared.global [%0], [%1], 16;" :: "r"(saddr), "l"(gaddr));
}
static __device__ __forceinline__ void cp_commit() {
    asm volatile("cp.async.commit_group;" ::: "memory");
}
static __device__ __forceinline__ uint32_t lds32(uint32_t addr) {
    uint32_t x;
    asm volatile("ld.shared.b32 %0, [%1];" : "=r"(x) : "r"(addr));
    return x;
}
// fp16 mma: D(16x8,f32) += A(16x16,f16,row) * B(16x8,f16,col)
static __device__ __forceinline__ void mma_f16(float* c, uint32_t a0, uint32_t a1,
                                               uint32_t a2, uint32_t a3,
                                               uint32_t b0, uint32_t b1) {
    asm volatile("mma.sync.aligned.m16n8k16.row.col.f32.f16.f16.f32 "
        "{%0,%1,%2,%3},{%4,%5,%6,%7},{%8,%9},{%0,%1,%2,%3};"
        : "+f"(c[0]), "+f"(c[1]), "+f"(c[2]), "+f"(c[3])
        : "r"(a0), "r"(a1), "r"(a2), "r"(a3), "r"(b0), "r"(b1));
}

#define GEMM_SMEM_BYTES (1024 + 6*16384)   // slack + 3 stages x (A16K + B16K)

// ---------------- tensor-core GEMM (mma.sync fp16, 4 warps 64x64) ------------
// identical math to R14
template<bool HC>
__global__ void __launch_bounds__(128, 2)
tc_gemm(int M, int K,
        const __half* __restrict__ A, const __half* __restrict__ W,
        const float* __restrict__ rowscale, const float* __restrict__ bias,
        const float* __restrict__ addC, void* __restrict__ Cv,
        __half* __restrict__ C2, const float* __restrict__ cs2a,
        const float* __restrict__ cs2b)
{
    extern __shared__ char smem_raw[];
    uint32_t base = (smem_u32(smem_raw) + 1023u) & ~1023u;
    uint32_t Aoff = base;
    uint32_t Boff = base + 3 * 16384;

    const int tid  = threadIdx.x;
    const int wid  = tid >> 5, lane = tid & 31;
    const int g    = lane >> 2, tig = lane & 3;
    const int rowA = blockIdx.y << 7;
    const int colB = blockIdx.x << 7;
    const int KT   = K >> 6;

    const int m_base = (wid >> 1) * 64;
    const int n_base = (wid & 1) * 64;

    uint32_t aRB[4][2], aMK[4][2], bRB[8], bMK[8];
    #pragma unroll
    for (int mi = 0; mi < 4; mi++) {
        int r0 = m_base + mi * 16 + g;
        int r1 = r0 + 8;
        aRB[mi][0] = (uint32_t)r0 << 7; aMK[mi][0] = ((uint32_t)r0 << 4) & 0x70u;
        aRB[mi][1] = (uint32_t)r1 << 7; aMK[mi][1] = ((uint32_t)r1 << 4) & 0x70u;
    }
    #pragma unroll
    for (int ni = 0; ni < 8; ni++) {
        int nr = n_base + ni * 8 + g;
        bRB[ni] = (uint32_t)nr << 7; bMK[ni] = ((uint32_t)nr << 4) & 0x70u;
    }

    float acc[4][8][4];
    #pragma unroll
    for (int mi = 0; mi < 4; mi++)
        #pragma unroll
        for (int ni = 0; ni < 8; ni++)
            #pragma unroll
            for (int q = 0; q < 4; q++) acc[mi][ni][q] = 0.f;

    #define LOAD_CHUNK(kt_, s_) do { \
        uint32_t _sA = Aoff + (s_) * 16384, _sB = Boff + (s_) * 16384; \
        const __half* _Ab = A + (size_t)rowA * K + (size_t)(kt_) * 64; \
        const __half* _Wb = W + (size_t)colB * K + (size_t)(kt_) * 64; \
        _Pragma("unroll") \
        for (int _i = 0; _i < 8; _i++) { \
            int _idx = tid + _i * 128; \
            int _r = _idx >> 3, _seg = _idx & 7; \
            uint32_t _b = ((uint32_t)_r << 7) + ((uint32_t)_seg << 4); \
            uint32_t _sw = _b ^ ((_b >> 3) & 0x70u); \
            cp16(_sA + _sw, _Ab + (size_t)_r * K + _seg * 8); \
            cp16(_sB + _sw, _Wb + (size_t)_r * K + _seg * 8); \
        } \
        cp_commit(); \
    } while (0)

    LOAD_CHUNK(0, 0);
    LOAD_CHUNK(1, 1);

    for (int kt = 0; kt < KT; kt++) {
        const int s = kt % 3;
        if (kt + 1 < KT) asm volatile("cp.async.wait_group 1;" ::: "memory");
        else             asm volatile("cp.async.wait_group 0;" ::: "memory");
        __syncthreads();
        if (kt + 2 < KT) LOAD_CHUNK(kt + 2, (kt + 2) % 3);

        const uint32_t aS = Aoff + s * 16384;
        const uint32_t bS = Boff + s * 16384;
        #pragma unroll
        for (int kk = 0; kk < 4; kk++) {
            const uint32_t c0b = (uint32_t)(kk * 32 + 4 * tig);
            const uint32_t c1b = c0b + 16u;
            uint32_t bf[8][2];
            #pragma unroll
            for (int ni = 0; ni < 8; ni++) {
                bf[ni][0] = lds32(bS + bRB[ni] + (c0b ^ bMK[ni]));
                bf[ni][1] = lds32(bS + bRB[ni] + (c1b ^ bMK[ni]));
            }
            #pragma unroll
            for (int mi = 0; mi < 4; mi++) {
                uint32_t a0 = lds32(aS + aRB[mi][0] + (c0b ^ aMK[mi][0]));
                uint32_t a1 = lds32(aS + aRB[mi][1] + (c0b ^ aMK[mi][1]));
                uint32_t a2 = lds32(aS + aRB[mi][0] + (c1b ^ aMK[mi][0]));
                uint32_t a3 = lds32(aS + aRB[mi][1] + (c1b ^ aMK[mi][1]));
                #pragma unroll
                for (int ni = 0; ni < 8; ni++)
                    mma_f16(acc[mi][ni], a0, a1, a2, a3, bf[ni][0], bf[ni][1]);
            }
        }
    }

    float*  Cf = (float*)Cv;
    __half* Ch = (__half*)Cv;
    #pragma unroll
    for (int mi = 0; mi < 4; mi++) {
        const int row0 = rowA + m_base + mi * 16 + g;
        const int row1 = row0 + 8;
        const float rs0 = rowscale ? rowscale[row0] : 1.0f;
        const float rs1 = rowscale ? rowscale[row1] : 1.0f;
        #pragma unroll
        for (int ni = 0; ni < 8; ni++) {
            const int col = colB + n_base + ni * 8 + 2 * tig;
            float2 bv = *(const float2*)(bias + col);
            size_t o0 = (size_t)row0 * M + col;
            size_t o1 = (size_t)row1 * M + col;
            float2 v0, v1;
            v0.x = acc[mi][ni][0] * rs0 + bv.x;
            v0.y = acc[mi][ni][1] * rs0 + bv.y;
            v1.x = acc[mi][ni][2] * rs1 + bv.x;
            v1.y = acc[mi][ni][3] * rs1 + bv.y;
            if (addC) {
                float2 r0 = *(const float2*)(addC + o0);
                float2 r1 = *(const float2*)(addC + o1);
                v0.x += r0.x; v0.y += r0.y;
                v1.x += r1.x; v1.y += r1.y;
            }
            if (HC) {
                *(__half2*)(Ch + o0) = __floats2half2_rn(v0.x, v0.y);
                *(__half2*)(Ch + o1) = __floats2half2_rn(v1.x, v1.y);
            } else {
                *(float2*)(Cf + o0) = v0;
                *(float2*)(Cf + o1) = v1;
            }
            if (C2) {
                float2 w0, w1;
                if (cs2a) {
                    float2 sa = *(const float2*)(cs2a + col);
                    float2 sb = *(const float2*)(cs2b + col);
                    w0.x = v0.x * sa.x * sb.x; w0.y = v0.y * sa.y * sb.y;
                    w1.x = v1.x * sa.x * sb.x; w1.y = v1.y * sa.y * sb.y;
                } else {
                    w0 = v0; w1 = v1;
                }
                *(__half2*)(C2 + o0) = __floats2half2_rn(w0.x, w0.y);
                *(__half2*)(C2 + o1) = __floats2half2_rn(w1.x, w1.y);
            }
        }
    }
    #undef LOAD_CHUNK
}

// ------- merged f/c/g weight pre-scale -> fp16 -------------------------------
__global__ void wscale3_kernel(const float4* __restrict__ Wf, const float4* __restrict__ Wc,
                               const float4* __restrict__ Wg, const float* __restrict__ c1,
                               const float* __restrict__ cf, const float* __restrict__ cc,
                               const float* __restrict__ cg, __half2* __restrict__ Wo) {
    const int tD = DDe / 4;
    int i = blockIdx.x * blockDim.x + threadIdx.x;
    if (i >= 3 * tD) return;
    int seg = i / tD, j = i % tD;
    int k4 = j % (Dd / 4);
    const float4* W = (seg == 0) ? Wf : (seg == 1) ? Wc : Wg;
    const float* c2 = (seg == 0) ? cf : (seg == 1) ? cc : cg;
    float4 w = W[j];
    float4 a = ((const float4*)c1)[k4];
    float4 b = ((const float4*)c2)[k4];
    Wo[2*i    ] = __floats2half2_rn(w.x * a.x * b.x, w.y * a.y * b.y);
    Wo[2*i + 1] = __floats2half2_rn(w.z * a.z * b.z, w.w * a.w * b.w);
}

// ---------------- concatenated f/c/g bias ------------------------------------
__global__ void bias3_kernel(const float* __restrict__ bf, const float* __restrict__ bc,
                             const float* __restrict__ bg, float* __restrict__ out) {
    int j = blockIdx.x * blockDim.x + threadIdx.x;
    int seg = j / Dd, d = j % Dd;
    out[j] = (seg == 0) ? bf[d] : (seg == 1) ? bc[d] : bg[d];
}

// ---------------- weight pre-convert -> fp16 ---------------------------------
__global__ void wcvt_kernel(const float4* __restrict__ W, __half2* __restrict__ Wo,
                            int total4) {
    int i = blockIdx.x * blockDim.x + threadIdx.x;
    if (i >= total4) return;
    float4 w = W[i];
    Wo[2*i    ] = __floats2half2_rn(w.x, w.y);
    Wo[2*i + 1] = __floats2half2_rn(w.z, w.w);
}

// ---------------- small helpers ----------------------------------------------
__device__ __forceinline__ float sigm(float x) { return 1.f / (1.f + __expf(-x)); }

__device__ __forceinline__ float blockReduce1(float s1) {
    __shared__ float r1[256];
    int t = threadIdx.x;
    r1[t] = s1; __syncthreads();
    for (int s = 128; s > 0; s >>= 1) {
        if (t < s) r1[t] += r1[t+s];
        __syncthreads();
    }
    float v = r1[0];
    __syncthreads();
    return v;
}
__device__ __forceinline__ void blockReduce2(float& s1, float& s2) {
    __shared__ float r1[256], r2[256];
    int t = threadIdx.x;
    r1[t] = s1; r2[t] = s2; __syncthreads();
    for (int s = 128; s > 0; s >>= 1) {
        if (t < s) { r1[t] += r1[t+s]; r2[t] += r2[t+s]; }
        __syncthreads();
    }
    s1 = r1[0]; s2 = r2[0];
    __syncthreads();
}

// ---------------- lb = cumsum(softmax(weight_l)) - weight_l[:, :1] -----------
__global__ void lb_kernel(const float* __restrict__ wl) {
    __shared__ float sm[Dd];
    __shared__ float red[256];
    int i = blockIdx.x;
    const float* w = wl + i * Dd;
    int t = threadIdx.x;
    float mx = -1e30f;
    for (int d = t; d < Dd; d += 256) mx = fmaxf(mx, w[d]);
    red[t] = mx; __syncthreads();
    for (int s = 128; s > 0; s >>= 1) { if (t < s) red[t] = fmaxf(red[t], red[t+s]); __syncthreads(); }
    mx = red[0]; __syncthreads();
    float sum = 0.f;
    for (int d = t; d < Dd; d += 256) { float e = expf(w[d] - mx); sm[d] = e; sum += e; }
    red[t] = sum; __syncthreads();
    for (int s = 128; s > 0; s >>= 1) { if (t < s) red[t] += red[t+s]; __syncthreads(); }
    float Z = red[0];
    float w0 = w[0];
    __syncthreads();
    for (int d = t; d < Dd; d += 256) {
        float c = 0.f;
        for (int k = 0; k <= d; k++) c += sm[k];
        g_LB[i * Dd + d] = c / Z - w0;
    }
}

// ---------------- y = emb[x]; yt = half(y) ------------------------------------
__global__ void embed_kernel(const int* __restrict__ x, const float* __restrict__ emb) {
    int idx = blockIdx.x * blockDim.x + threadIdx.x;
    int n  = idx / (Dd/4);
    int d4 = idx % (Dd/4);
    int b = n / Tt, t = n % Tt;
    int tok = x[b * Tt + t];
    float4 v = ((const float4*)(emb + (size_t)tok * Dd))[d4];
    ((float4*)g_Y)[(size_t)n * (Dd/4) + d4] = v;
    __half2* yt = (__half2*)g_YT + (size_t)n * (Dd/2) + d4 * 2;
    yt[0] = __floats2half2_rn(v.x, v.y);
    yt[1] = __floats2half2_rn(v.z, v.w);
}

// ---------------- row rms stats (combined double-rms scale) ------------------
__global__ void rms_rows_kernel(const float* __restrict__ X, const float* __restrict__ w,
                                float* __restrict__ out, int D) {
    int n = blockIdx.x;
    const float* x = X + (size_t)n * D;
    float s1 = 0.f, s2 = 0.f;
    for (int d = threadIdx.x; d < D; d += 256) {
        float v = x[d];
        s1 += v * v;
        float vw = v * w[d]; s2 += vw * vw;
    }
    blockReduce2(s1, s2);
    if (threadIdx.x == 0) {
        float r1 = rsqrtf(s1 / D + EPSf);
        float r2 = rsqrtf(r1 * r1 * s2 / D + EPSf);
        out[n] = r1 * r2;
    }
}

// ---------------- chunked linear-recurrence scan (Z fp16, [NN][3D]) ----------
__global__ void scan1_kernel(const __half* __restrict__ Z, const float* __restrict__ lbrow) {
    int id = blockIdx.x * blockDim.x + threadIdx.x;
    int d = id % Dd;
    int c = (id / Dd) % CH;
    int b = id / (Dd * CH);
    float l = lbrow[d];
    size_t base = ((size_t)b * Tt + (size_t)c * TC) * (3 * Dd) + d;
    float a = 1.f, h = 0.f;
    for (int t = 0; t < TC; t++) {
        size_t o = base + (size_t)t * (3 * Dd);
        float f  = l + (1.f - l) * sigm(__half2float(Z[o]));
        float zv = __half2float(Z[o + Dd]);
        float cc = zv * sigm(zv);
        h = f * h + (1.f - f) * cc;
        a *= f;
    }
    g_SA[id] = a;
    g_SB[id] = h;
}
__global__ void scan2_kernel(const __half* __restrict__ Z, const float* __restrict__ lbrow,
                             __half* __restrict__ H) {
    int id = blockIdx.x * blockDim.x + threadIdx.x;
    int d = id % Dd;
    int c = (id / Dd) % CH;
    int b = id / (Dd * CH);
    float l = lbrow[d];
    float h = 0.f;
    for (int j = 0; j < c; j++) {
        int sid = (b * CH + j) * Dd + d;
        h = g_SA[sid] * h + g_SB[sid];
    }
    size_t base = ((size_t)b * Tt + (size_t)c * TC) * (3 * Dd) + d;
    size_t hbase = ((size_t)b * Tt + (size_t)c * TC) * Dd + d;
    for (int t = 0; t < TC; t++) {
        size_t o = base + (size_t)t * (3 * Dd);
        float f  = l + (1.f - l) * sigm(__half2float(Z[o]));
        float zv = __half2float(Z[o + Dd]);
        float cc = zv * sigm(zv);
        h = f * h + (1.f - f) * cc;
        H[hbase + (size_t)t * Dd] = __float2half_rn(h);
    }
}

// ---------------- fused: rz = rms(ZG); s = xg*h*sig(h); S = half(s*wgo); rB --
__global__ void s_fused_kernel(const __half* __restrict__ Z, const float* __restrict__ wnorm,
                               const __half* __restrict__ H, const float* __restrict__ wgo,
                               __half* __restrict__ S, float* __restrict__ rs_out) {
    __shared__ float zbuf[Dd];
    int n = blockIdx.x;
    const __half* zg = Z + (size_t)n * (3 * Dd) + 2 * Dd;
    float s1 = 0.f;
    for (int d = threadIdx.x; d < Dd; d += 256) {
        float v = __half2float(zg[d]);
        zbuf[d] = v;
        s1 += v * v;
    }
    float rz = rsqrtf(blockReduce1(s1) / Dd + EPSf);
    float s2 = 0.f;
    for (int d = threadIdx.x; d < Dd; d += 256) {
        size_t o = (size_t)n * Dd + d;
        float xg = zbuf[d] * rz * wnorm[d];
        float h  = __half2float(H[o]);
        float s  = xg * h * sigm(h);
        S[o] = __float2half_rn(s * wgo[d]);
        s2 += s * s;
    }
    s2 = blockReduce1(s2);
    if (threadIdx.x == 0) rs_out[n] = rsqrtf(s2 / Dd + EPSf);
}

// ---------------- fused GLU: gp = silu(u0)*u1; GP = half(gp*gwd); rg ---------
__global__ void glu_kernel(const __half* __restrict__ UU, const float* __restrict__ gwd,
                           __half* __restrict__ GP, float* __restrict__ rg) {
    int n = blockIdx.x;
    const __half* u = UU + (size_t)n * 2 * Ii;
    float s2 = 0.f;
    for (int k = threadIdx.x; k < Ii; k += 256) {
        float a = __half2float(u[k]), b = __half2float(u[Ii + k]);
        float gv = a * sigm(a) * b;
        GP[(size_t)n * Ii + k] = __float2half_rn(gv * gwd[k]);
        s2 += gv * gv;
    }
    s2 = blockReduce1(s2);
    if (threadIdx.x == 0) rg[n] = rsqrtf(s2 / Ii + EPSf);
}

// ---------------- launcher ----------------------------------------------------
extern "C" void kernel_launch(void* const* d_in, const int* in_sizes, int n_in,
                              void* d_out, int out_size) {
    const int*   x       = (const int*)  d_in[0];
    const float* emb     = (const float*)d_in[1];
    const float* wg_in   = (const float*)d_in[2];
    const float* wg_f    = (const float*)d_in[3];
    const float* wg_c    = (const float*)d_in[4];
    const float* wg_g    = (const float*)d_in[5];
    const float* wg_norm = (const float*)d_in[6];
    const float* lf_w    = (const float*)d_in[7];
    const float* lf_b    = (const float*)d_in[8];
    const float* lc_w    = (const float*)d_in[9];
    const float* lc_b    = (const float*)d_in[10];
    const float* lg_w    = (const float*)d_in[11];
    const float* lg_b    = (const float*)d_in[12];
    const float* weight_l= (const float*)d_in[13];
    const float* wg_o    = (const float*)d_in[14];
    const float* lo_w    = (const float*)d_in[15];
    const float* lo_b    = (const float*)d_in[16];
    const float* glu_wg  = (const float*)d_in[17];
    const float* glu_wgo = (const float*)d_in[18];
    const float* glu_wd  = (const float*)d_in[19];
    const float* lu_w    = (const float*)d_in[20];
    const float* lu_b    = (const float*)d_in[21];
    const float* ln_w    = (const float*)d_in[22];
    const float* ln_b    = (const float*)d_in[23];
    const float* out_w   = (const float*)d_in[24];
    const float* out_b   = (const float*)d_in[25];
    float* out = (float*)d_out;

    float *pY, *pXO, *prA, *prB, *pLB, *pB3s;
    __half *pYT, *pZ, *pH, *pS, *pXS, *pUU, *pGP, *pWP, *pWO;
    cudaGetSymbolAddress((void**)&pY,  g_Y);
    cudaGetSymbolAddress((void**)&pYT, g_YT);
    cudaGetSymbolAddress((void**)&pZ,  g_Z);
    cudaGetSymbolAddress((void**)&pH,  g_H);
    cudaGetSymbolAddress((void**)&pS,  g_S);
    cudaGetSymbolAddress((void**)&pXO, g_XO);
    cudaGetSymbolAddress((void**)&pXS, g_XS);
    cudaGetSymbolAddress((void**)&pUU, g_UU);
    cudaGetSymbolAddress((void**)&pGP, g_GP);
    cudaGetSymbolAddress((void**)&pWP, g_WP);
    cudaGetSymbolAddress((void**)&pWO, g_WO);
    cudaGetSymbolAddress((void**)&pB3s, g_B3s);
    cudaGetSymbolAddress((void**)&prA, g_rA);
    cudaGetSymbolAddress((void**)&prB, g_rB);
    cudaGetSymbolAddress((void**)&pLB, g_LB);

    cudaFuncSetAttribute(tc_gemm<false>, cudaFuncAttributeMaxDynamicSharedMemorySize, GEMM_SMEM_BYTES);
    cudaFuncSetAttribute(tc_gemm<true>,  cudaFuncAttributeMaxDynamicSharedMemorySize, GEMM_SMEM_BYTES);

    // side stream + events (host resources; lazily created, reused every call)
    static cudaStream_t side = nullptr;
    static cudaEvent_t evFork = nullptr;
    static cudaEvent_t evPrep[NBk + 1];
    if (!side) {
        cudaStreamCreate(&side);
        cudaEventCreateWithFlags(&evFork, cudaEventDisableTiming);
        for (int i = 0; i <= NBk; i++)
            cudaEventCreateWithFlags(&evPrep[i], cudaEventDisableTiming);
    }

    const int tD = DDe / 4;
    const int tU = 2 * IDe / 4;
    const int tN = IDe / 4;

    // ---- fork: all weight prep runs on the side stream, overlapped ----
    cudaEventRecord(evFork, 0);
    cudaStreamWaitEvent(side, evFork, 0);
    for (int i = 0; i < NBk; i++) {
        __half* wp = pWP + (size_t)i * WPB;
        bias3_kernel<<<(3 * Dd) / 256, 256, 0, side>>>(lf_b + i*Dd, lc_b + i*Dd, lg_b + i*Dd,
                                                       pB3s + i * 3 * Dd);
        wscale3_kernel<<<(3 * tD + 255) / 256, 256, 0, side>>>(
            (const float4*)(lf_w + (size_t)i*DDe), (const float4*)(lc_w + (size_t)i*DDe),
            (const float4*)(lg_w + (size_t)i*DDe),
            wg_in + i*Dd, wg_f + i*Dd, wg_c + i*Dd, wg_g + i*Dd, (__half2*)wp);
        wcvt_kernel<<<(tD + 255) / 256, 256, 0, side>>>(
            (const float4*)(lo_w + (size_t)i*DDe), (__half2*)(wp + 3*DDe), tD);
        wcvt_kernel<<<(tU + 255) / 256, 256, 0, side>>>(
            (const float4*)(lu_w + (size_t)i*2*IDe), (__half2*)(wp + 4*DDe), tU);
        wcvt_kernel<<<(tN + 255) / 256, 256, 0, side>>>(
            (const float4*)(ln_w + (size_t)i*IDe), (__half2*)(wp + 4*DDe + 2*IDe), tN);
        cudaEventRecord(evPrep[i], side);
    }
    wcvt_kernel<<<(Vv * Dd / 4 + 255) / 256, 256, 0, side>>>(
        (const float4*)out_w, (__half2*)pWO, Vv * Dd / 4);
    cudaEventRecord(evPrep[NBk], side);

    // ---- main chain ----
    lb_kernel<<<NBk, 256>>>(weight_l);
    embed_kernel<<<(NN * Dd / 4) / 256, 256>>>(x, emb);

    dim3 gFCG(3 * Dd / 128, NN / 128);
    dim3 gD(Dd / 128, NN / 128);
    dim3 gU(2 * Ii / 128, NN / 128);
    dim3 gV(Vv / 128, NN / 128);
    const int scanBlocks = (Bb * CH * Dd) / 256;

    for (int i = 0; i < NBk; i++) {
        const float* wgn  = wg_norm + i * Dd;
        const float* wgo  = wg_o    + i * Dd;
        const float* gwg  = glu_wg  + i * Dd;
        const float* gwgo = glu_wgo + i * Dd;
        const float* gwd  = glu_wd  + i * Ii;
        __half* wp = pWP + (size_t)i * WPB;

        rms_rows_kernel<<<NN, 256>>>(pY, wg_in + i*Dd, prA, Dd);

        cudaStreamWaitEvent(0, evPrep[i], 0);   // join: block i's weights ready

        // merged f/c/g GEMM -> Z (fp16) = [NN][ZF|ZC|ZG]
        tc_gemm<true><<<gFCG, 128, GEMM_SMEM_BYTES>>>(3 * Dd, Dd, pYT, wp, prA,
                                                      pB3s + i * 3 * Dd,
                                                      nullptr, pZ, nullptr, nullptr, nullptr);

        // gated recurrence over t: 2-pass chunked scan
        scan1_kernel<<<scanBlocks, 256>>>(pZ, pLB + i * Dd);
        scan2_kernel<<<scanBlocks, 256>>>(pZ, pLB + i * Dd, pH);

        // fused: x_g row-rms + s = x_g*h*sig(h), S = half(s*wgo)
        s_fused_kernel<<<NN, 256>>>(pZ, wgn, pH, wgo, pS, prB);

        // x_o = y + rms(s, wg_o) @ lo_w^T + lo_b ; also XS = half(XO*gwg*gwgo)
        tc_gemm<false><<<gD, 128, GEMM_SMEM_BYTES>>>(Dd, Dd, pS, wp + 3*DDe, prB,
                                                     lo_b + i*Dd, pY, pXO, pXS, gwg, gwgo);

        // GLU up-proj row scale, then UU (fp16) = XS @ lu_w^T + lu_b
        rms_rows_kernel<<<NN, 256>>>(pXO, gwg, prA, Dd);
        tc_gemm<true><<<gU, 128, GEMM_SMEM_BYTES>>>(2 * Ii, Dd, pXS, wp + 4*DDe, prA,
                                                    lu_b + (size_t)i*2*Ii, nullptr, pUU,
                                                    nullptr, nullptr, nullptr);

        // fused GLU gate (col scale gwd folded, fp16)
        glu_kernel<<<NN, 256>>>(pUU, gwd, pGP, prB);

        // y_next = x_o + rms(gp, glu_wd) @ ln_w^T + ln_b ; also YT = half(y_next)
        tc_gemm<false><<<gD, 128, GEMM_SMEM_BYTES>>>(Dd, Ii, pGP, wp + 4*DDe + 2*IDe, prB,
                                                     ln_b + i*Dd, pXO, pY, pYT,
                                                     nullptr, nullptr);
    }

    // logits = yt @ half(out_w)^T + out_b  -> [B,T,V]
    cudaStreamWaitEvent(0, evPrep[NBk], 0);
    tc_gemm<false><<<gV, 128, GEMM_SMEM_BYTES>>>(Vv, Dd, pYT, pWO, nullptr, out_b,
                                                 nullptr, out, nullptr, nullptr, nullptr);
}

// round 17
// speedup vs baseline: 1.0695x; 1.0695x over previous
#include <cuda_runtime.h>
#include <cuda_fp16.h>
#include <cstdint>
#include <math.h>

#define NBk 4
#define Bb  8
#define Tt  1024
#define Dd  1024
#define Vv  256
#define Ii  2816
#define NN  (Bb*Tt)      // 8192 tokens
#define EPSf 1e-6f
#define TC  128          // scan chunk length
#define CH  (Tt/TC)      // 8 chunks
#define GScols 44        // (2*Ii/128) CTcolumn tiles in the lu GEMM

#define DDe (Dd*Dd)
#define IDe (Ii*Dd)

// ---------------- scratch (device globals; no allocation allowed) ------------
__device__ float  g_Y [NN*Dd];
__device__ __half g_YT[NN*Dd];             // fp16 copy of Y (GEMM A operand)
__device__ __half g_Z [(size_t)NN*3*Dd];   // [NN][3D]: ZF | ZC | ZG  (fp16)
__device__ __half g_H [NN*Dd];             // fp16
__device__ __half g_S [NN*Dd];
__device__ float  g_XO[NN*Dd];
__device__ __half g_XS[NN*Dd];             // fp16 scaled copy of XO
__device__ __half g_GP[(size_t)NN*Ii];
__device__ __half g_WS[(size_t)2*Ii*Dd];   // fp16 weight scratch (max 2I x D)
__device__ float  g_GS[(size_t)NN*GScols]; // per-(row,CTA) partial sum of gp^2
__device__ float  g_B3[3*Dd];              // concatenated f/c/g bias
__device__ float  g_BLU[2*Ii];             // permuted lu bias
__device__ float  g_rA[NN];
__device__ float  g_rB[NN];
__device__ float  g_LB[NBk*Dd];
__device__ float  g_SA[Bb*CH*Dd];
__device__ float  g_SB[Bb*CH*Dd];

// ---------------- PTX helpers -------------------------------------------------
__device__ __forceinline__ uint32_t smem_u32(const void* p) {
    uint32_t a;
    asm("{ .reg .u64 t; cvta.to.shared.u64 t, %1; cvt.u32.u64 %0, t; }" : "=r"(a) : "l"(p));
    return a;
}
static __device__ __forceinline__ void cp16(uint32_t saddr, const void* gaddr) {
    asm volatile("cp.async.cg.shared.global [%0], [%1], 16;" :: "r"(saddr), "l"(gaddr));
}
static __device__ __forceinline__ void cp_commit() {
    asm volatile("cp.async.commit_group;" ::: "memory");
}
static __device__ __forceinline__ uint32_t lds32(uint32_t addr) {
    uint32_t x;
    asm volatile("ld.shared.b32 %0, [%1];" : "=r"(x) : "r"(addr));
    return x;
}
__device__ __forceinline__ float sigm(float x) { return 1.f / (1.f + __expf(-x)); }
// fp16 mma: D(16x8,f32) += A(16x16,f16,row) * B(16x8,f16,col)
static __device__ __forceinline__ void mma_f16(float* c, uint32_t a0, uint32_t a1,
                                               uint32_t a2, uint32_t a3,
                                               uint32_t b0, uint32_t b1) {
    asm volatile("mma.sync.aligned.m16n8k16.row.col.f32.f16.f16.f32 "
        "{%0,%1,%2,%3},{%4,%5,%6,%7},{%8,%9},{%0,%1,%2,%3};"
        : "+f"(c[0]), "+f"(c[1]), "+f"(c[2]), "+f"(c[3])
        : "r"(a0), "r"(a1), "r"(a2), "r"(a3), "r"(b0), "r"(b1));
}

#define GEMM_SMEM_BYTES (1024 + 6*16384)   // slack + 3 stages x (A16K + B16K)

// ---------------- tensor-core GEMM (mma.sync fp16, 4 warps 64x64) ------------
// A [N,K], W [M,K] fp16 row-major, K mult of 64. grid (M/128, N/128), 128 thr.
// GLU=false:
//   HC=false: C=float*, C[n,m] = rs[n]*acc + bias[m] (+ addC[n,m])
//   HC=true : C=__half*, same value fp16
//   optional C2 (fp16): cs2a? C*cs2a*cs2b : C
// GLU=true (lu projection with row-interleaved W):
//   u0 = v.x, u1 = v.y per column pair; gp = u0*sigm(u0)*u1
//   C2[n, col/2] = half(gp * cs2a[col/2]);   GSp[n*GScols + bx] = sum gp^2 (CTA partial)
template<bool HC, bool GLU>
__global__ void __launch_bounds__(128, 2)
tc_gemm(int M, int K,
        const __half* __restrict__ A, const __half* __restrict__ W,
        const float* __restrict__ rowscale, const float* __restrict__ bias,
        const float* __restrict__ addC, void* __restrict__ Cv,
        __half* __restrict__ C2, const float* __restrict__ cs2a,
        const float* __restrict__ cs2b, float* __restrict__ GSp)
{
    extern __shared__ char smem_raw[];
    uint32_t base = (smem_u32(smem_raw) + 1023u) & ~1023u;
    uint32_t Aoff = base;
    uint32_t Boff = base + 3 * 16384;

    const int tid  = threadIdx.x;
    const int wid  = tid >> 5, lane = tid & 31;
    const int g    = lane >> 2, tig = lane & 3;
    const int rowA = blockIdx.y << 7;
    const int colB = blockIdx.x << 7;
    const int KT   = K >> 6;

    const int m_base = (wid >> 1) * 64;
    const int n_base = (wid & 1) * 64;

    uint32_t aRB[4][2], aMK[4][2], bRB[8], bMK[8];
    #pragma unroll
    for (int mi = 0; mi < 4; mi++) {
        int r0 = m_base + mi * 16 + g;
        int r1 = r0 + 8;
        aRB[mi][0] = (uint32_t)r0 << 7; aMK[mi][0] = ((uint32_t)r0 << 4) & 0x70u;
        aRB[mi][1] = (uint32_t)r1 << 7; aMK[mi][1] = ((uint32_t)r1 << 4) & 0x70u;
    }
    #pragma unroll
    for (int ni = 0; ni < 8; ni++) {
        int nr = n_base + ni * 8 + g;
        bRB[ni] = (uint32_t)nr << 7; bMK[ni] = ((uint32_t)nr << 4) & 0x70u;
    }

    float acc[4][8][4];
    #pragma unroll
    for (int mi = 0; mi < 4; mi++)
        #pragma unroll
        for (int ni = 0; ni < 8; ni++)
            #pragma unroll
            for (int q = 0; q < 4; q++) acc[mi][ni][q] = 0.f;

    #define LOAD_CHUNK(kt_, s_) do { \
        uint32_t _sA = Aoff + (s_) * 16384, _sB = Boff + (s_) * 16384; \
        const __half* _Ab = A + (size_t)rowA * K + (size_t)(kt_) * 64; \
        const __half* _Wb = W + (size_t)colB * K + (size_t)(kt_) * 64; \
        _Pragma("unroll") \
        for (int _i = 0; _i < 8; _i++) { \
            int _idx = tid + _i * 128; \
            int _r = _idx >> 3, _seg = _idx & 7; \
            uint32_t _b = ((uint32_t)_r << 7) + ((uint32_t)_seg << 4); \
            uint32_t _sw = _b ^ ((_b >> 3) & 0x70u); \
            cp16(_sA + _sw, _Ab + (size_t)_r * K + _seg * 8); \
            cp16(_sB + _sw, _Wb + (size_t)_r * K + _seg * 8); \
        } \
        cp_commit(); \
    } while (0)

    LOAD_CHUNK(0, 0);
    LOAD_CHUNK(1, 1);

    for (int kt = 0; kt < KT; kt++) {
        const int s = kt % 3;
        if (kt + 1 < KT) asm volatile("cp.async.wait_group 1;" ::: "memory");
        else             asm volatile("cp.async.wait_group 0;" ::: "memory");
        __syncthreads();
        if (kt + 2 < KT) LOAD_CHUNK(kt + 2, (kt + 2) % 3);

        const uint32_t aS = Aoff + s * 16384;
        const uint32_t bS = Boff + s * 16384;
        #pragma unroll
        for (int kk = 0; kk < 4; kk++) {
            const uint32_t c0b = (uint32_t)(kk * 32 + 4 * tig);
            const uint32_t c1b = c0b + 16u;
            uint32_t bf[8][2];
            #pragma unroll
            for (int ni = 0; ni < 8; ni++) {
                bf[ni][0] = lds32(bS + bRB[ni] + (c0b ^ bMK[ni]));
                bf[ni][1] = lds32(bS + bRB[ni] + (c1b ^ bMK[ni]));
            }
            #pragma unroll
            for (int mi = 0; mi < 4; mi++) {
                uint32_t a0 = lds32(aS + aRB[mi][0] + (c0b ^ aMK[mi][0]));
                uint32_t a1 = lds32(aS + aRB[mi][1] + (c0b ^ aMK[mi][1]));
                uint32_t a2 = lds32(aS + aRB[mi][0] + (c1b ^ aMK[mi][0]));
                uint32_t a3 = lds32(aS + aRB[mi][1] + (c1b ^ aMK[mi][1]));
                #pragma unroll
                for (int ni = 0; ni < 8; ni++)
                    mma_f16(acc[mi][ni], a0, a1, a2, a3, bf[ni][0], bf[ni][1]);
            }
        }
    }

    // ---- epilogue ----
    float*  Cf = (float*)Cv;
    __half* Ch = (__half*)Cv;
    float r0s[4], r1s[4];
    if (GLU) {
        #pragma unroll
        for (int mi = 0; mi < 4; mi++) { r0s[mi] = 0.f; r1s[mi] = 0.f; }
    }
    #pragma unroll
    for (int mi = 0; mi < 4; mi++) {
        const int row0 = rowA + m_base + mi * 16 + g;
        const int row1 = row0 + 8;
        const float rs0 = rowscale ? rowscale[row0] : 1.0f;
        const float rs1 = rowscale ? rowscale[row1] : 1.0f;
        #pragma unroll
        for (int ni = 0; ni < 8; ni++) {
            const int col = colB + n_base + ni * 8 + 2 * tig;
            float2 bv = *(const float2*)(bias + col);
            size_t o0 = (size_t)row0 * M + col;
            size_t o1 = (size_t)row1 * M + col;
            float2 v0, v1;
            v0.x = acc[mi][ni][0] * rs0 + bv.x;
            v0.y = acc[mi][ni][1] * rs0 + bv.y;
            v1.x = acc[mi][ni][2] * rs1 + bv.x;
            v1.y = acc[mi][ni][3] * rs1 + bv.y;
            if (GLU) {
                const int k0 = col >> 1;
                const float gw = cs2a[k0];
                float gp0 = v0.x * sigm(v0.x) * v0.y;
                float gp1 = v1.x * sigm(v1.x) * v1.y;
                C2[(size_t)row0 * (M >> 1) + k0] = __float2half_rn(gp0 * gw);
                C2[(size_t)row1 * (M >> 1) + k0] = __float2half_rn(gp1 * gw);
                r0s[mi] += gp0 * gp0;
                r1s[mi] += gp1 * gp1;
            } else {
                if (addC) {
                    float2 a0v = *(const float2*)(addC + o0);
                    float2 a1v = *(const float2*)(addC + o1);
                    v0.x += a0v.x; v0.y += a0v.y;
                    v1.x += a1v.x; v1.y += a1v.y;
                }
                if (HC) {
                    *(__half2*)(Ch + o0) = __floats2half2_rn(v0.x, v0.y);
                    *(__half2*)(Ch + o1) = __floats2half2_rn(v1.x, v1.y);
                } else {
                    *(float2*)(Cf + o0) = v0;
                    *(float2*)(Cf + o1) = v1;
                }
                if (C2) {
                    float2 w0, w1;
                    if (cs2a) {
                        float2 sa = *(const float2*)(cs2a + col);
                        float2 sb = *(const float2*)(cs2b + col);
                        w0.x = v0.x * sa.x * sb.x; w0.y = v0.y * sa.y * sb.y;
                        w1.x = v1.x * sa.x * sb.x; w1.y = v1.y * sa.y * sb.y;
                    } else {
                        w0 = v0; w1 = v1;
                    }
                    *(__half2*)(C2 + o0) = __floats2half2_rn(w0.x, w0.y);
                    *(__half2*)(C2 + o1) = __floats2half2_rn(w1.x, w1.y);
                }
            }
        }
    }
    if (GLU) {
        // deterministic per-row reduction: quad shfl -> smem combine -> GS partial
        float* ssum = (float*)smem_raw + ((Aoff - smem_u32(smem_raw)) >> 2);
        __syncthreads();   // mainloop smem dead; safe to reuse
        #pragma unroll
        for (int mi = 0; mi < 4; mi++) {
            r0s[mi] += __shfl_xor_sync(0xffffffffu, r0s[mi], 1);
            r0s[mi] += __shfl_xor_sync(0xffffffffu, r0s[mi], 2);
            r1s[mi] += __shfl_xor_sync(0xffffffffu, r1s[mi], 1);
            r1s[mi] += __shfl_xor_sync(0xffffffffu, r1s[mi], 2);
        }
        if (tig == 0) {
            #pragma unroll
            for (int mi = 0; mi < 4; mi++) {
                ssum[((wid * 4 + mi) * 2 + 0) * 8 + g] = r0s[mi];
                ssum[((wid * 4 + mi) * 2 + 1) * 8 + g] = r1s[mi];
            }
        }
        __syncthreads();
        int r = tid;            // 128 rows per CTA
        int mh = r >> 6, mi = (r >> 4) & 3, hf = (r >> 3) & 1, gg = r & 7;
        float sum = ssum[(((mh * 2 + 0) * 4 + mi) * 2 + hf) * 8 + gg]
                  + ssum[(((mh * 2 + 1) * 4 + mi) * 2 + hf) * 8 + gg];
        GSp[(size_t)(rowA + mh * 64 + mi * 16 + hf * 8 + gg) * GScols + blockIdx.x] = sum;
    }
    #undef LOAD_CHUNK
}

// ---------------- glu row-rms from CTA partials ------------------------------
__global__ void glu_rms_kernel(const float* __restrict__ GS, float* __restrict__ rg) {
    int n = blockIdx.x * blockDim.x + threadIdx.x;
    if (n >= NN) return;
    float s = 0.f;
    #pragma unroll
    for (int j = 0; j < GScols; j++) s += GS[(size_t)n * GScols + j];
    rg[n] = rsqrtf(s / Ii + EPSf);
}

// ------- merged f/c/g weight pre-scale -> fp16 -------------------------------
__global__ void wscale3_kernel(const float4* __restrict__ Wf, const float4* __restrict__ Wc,
                               const float4* __restrict__ Wg, const float* __restrict__ c1,
                               const float* __restrict__ cf, const float* __restrict__ cc,
                               const float* __restrict__ cg, __half2* __restrict__ Wo) {
    const int tD = DDe / 4;
    int i = blockIdx.x * blockDim.x + threadIdx.x;
    if (i >= 3 * tD) return;
    int seg = i / tD, j = i % tD;
    int k4 = j % (Dd / 4);
    const float4* W = (seg == 0) ? Wf : (seg == 1) ? Wc : Wg;
    const float* c2 = (seg == 0) ? cf : (seg == 1) ? cc : cg;
    float4 w = W[j];
    float4 a = ((const float4*)c1)[k4];
    float4 b = ((const float4*)c2)[k4];
    Wo[2*i    ] = __floats2half2_rn(w.x * a.x * b.x, w.y * a.y * b.y);
    Wo[2*i + 1] = __floats2half2_rn(w.z * a.z * b.z, w.w * a.w * b.w);
}

// ---------------- concatenated f/c/g bias ------------------------------------
__global__ void bias3_kernel(const float* __restrict__ bf, const float* __restrict__ bc,
                             const float* __restrict__ bg) {
    int j = blockIdx.x * blockDim.x + threadIdx.x;
    int seg = j / Dd, d = j % Dd;
    g_B3[j] = (seg == 0) ? bf[d] : (seg == 1) ? bc[d] : bg[d];
}

// ---------------- weight pre-convert -> fp16 ---------------------------------
__global__ void wcvt_kernel(const float4* __restrict__ W, __half2* __restrict__ Wo,
                            int total4) {
    int i = blockIdx.x * blockDim.x + threadIdx.x;
    if (i >= total4) return;
    float4 w = W[i];
    Wo[2*i    ] = __floats2half2_rn(w.x, w.y);
    Wo[2*i + 1] = __floats2half2_rn(w.z, w.w);
}

// -------- lu weight prep: interleave rows (2k<-k, 2k+1<-I+k), fp16 -----------
__global__ void wperm_lu_kernel(const float4* __restrict__ W, __half2* __restrict__ Wo) {
    int total4 = 2 * IDe / 4;
    int i = blockIdx.x * blockDim.x + threadIdx.x;
    if (i >= total4) return;
    int c4 = i % (Dd / 4);
    int rowp = i / (Dd / 4);
    int k = rowp >> 1, h = rowp & 1;
    int src = h ? (Ii + k) : k;
    float4 w = W[(size_t)src * (Dd / 4) + c4];
    Wo[2*i    ] = __floats2half2_rn(w.x, w.y);
    Wo[2*i + 1] = __floats2half2_rn(w.z, w.w);
}
__global__ void biasperm_lu_kernel(const float* __restrict__ b) {
    int j = blockIdx.x * blockDim.x + threadIdx.x;   // 2*Ii
    int k = j >> 1, h = j & 1;
    g_BLU[j] = b[h ? (Ii + k) : k];
}

// ---------------- small helpers ----------------------------------------------
__device__ __forceinline__ float blockReduce1(float s1) {
    __shared__ float r1[256];
    int t = threadIdx.x;
    r1[t] = s1; __syncthreads();
    for (int s = 128; s > 0; s >>= 1) {
        if (t < s) r1[t] += r1[t+s];
        __syncthreads();
    }
    float v = r1[0];
    __syncthreads();
    return v;
}
__device__ __forceinline__ void blockReduce2(float& s1, float& s2) {
    __shared__ float r1[256], r2[256];
    int t = threadIdx.x;
    r1[t] = s1; r2[t] = s2; __syncthreads();
    for (int s = 128; s > 0; s >>= 1) {
        if (t < s) { r1[t] += r1[t+s]; r2[t] += r2[t+s]; }
        __syncthreads();
    }
    s1 = r1[0]; s2 = r2[0];
    __syncthreads();
}

// ---------------- lb = cumsum(softmax(weight_l)) - weight_l[:, :1] -----------
__global__ void lb_kernel(const float* __restrict__ wl) {
    __shared__ float sm[Dd];
    __shared__ float red[256];
    int i = blockIdx.x;
    const float* w = wl + i * Dd;
    int t = threadIdx.x;
    float mx = -1e30f;
    for (int d = t; d < Dd; d += 256) mx = fmaxf(mx, w[d]);
    red[t] = mx; __syncthreads();
    for (int s = 128; s > 0; s >>= 1) { if (t < s) red[t] = fmaxf(red[t], red[t+s]); __syncthreads(); }
    mx = red[0]; __syncthreads();
    float sum = 0.f;
    for (int d = t; d < Dd; d += 256) { float e = expf(w[d] - mx); sm[d] = e; sum += e; }
    red[t] = sum; __syncthreads();
    for (int s = 128; s > 0; s >>= 1) { if (t < s) red[t] += red[t+s]; __syncthreads(); }
    float Z = red[0];
    float w0 = w[0];
    __syncthreads();
    for (int d = t; d < Dd; d += 256) {
        float c = 0.f;
        for (int k = 0; k <= d; k++) c += sm[k];
        g_LB[i * Dd + d] = c / Z - w0;
    }
}

// ---------------- y = emb[x]; yt = half(y) ------------------------------------
__global__ void embed_kernel(const int* __restrict__ x, const float* __restrict__ emb) {
    int idx = blockIdx.x * blockDim.x + threadIdx.x;
    int n  = idx / (Dd/4);
    int d4 = idx % (Dd/4);
    int b = n / Tt, t = n % Tt;
    int tok = x[b * Tt + t];
    float4 v = ((const float4*)(emb + (size_t)tok * Dd))[d4];
    ((float4*)g_Y)[(size_t)n * (Dd/4) + d4] = v;
    __half2* yt = (__half2*)g_YT + (size_t)n * (Dd/2) + d4 * 2;
    yt[0] = __floats2half2_rn(v.x, v.y);
    yt[1] = __floats2half2_rn(v.z, v.w);
}

// ---------------- row rms stats (combined double-rms scale) ------------------
__global__ void rms_rows_kernel(const float* __restrict__ X, const float* __restrict__ w,
                                float* __restrict__ out, int D) {
    int n = blockIdx.x;
    const float* x = X + (size_t)n * D;
    float s1 = 0.f, s2 = 0.f;
    for (int d = threadIdx.x; d < D; d += 256) {
        float v = x[d];
        s1 += v * v;
        float vw = v * w[d]; s2 += vw * vw;
    }
    blockReduce2(s1, s2);
    if (threadIdx.x == 0) {
        float r1 = rsqrtf(s1 / D + EPSf);
        float r2 = rsqrtf(r1 * r1 * s2 / D + EPSf);
        out[n] = r1 * r2;
    }
}

// ---------------- chunked linear-recurrence scan (Z fp16, [NN][3D]) ----------
__global__ void scan1_kernel(const __half* __restrict__ Z, const float* __restrict__ lbrow) {
    int id = blockIdx.x * blockDim.x + threadIdx.x;
    int d = id % Dd;
    int c = (id / Dd) % CH;
    int b = id / (Dd * CH);
    float l = lbrow[d];
    size_t base = ((size_t)b * Tt + (size_t)c * TC) * (3 * Dd) + d;
    float a = 1.f, h = 0.f;
    for (int t = 0; t < TC; t++) {
        size_t o = base + (size_t)t * (3 * Dd);
        float f  = l + (1.f - l) * sigm(__half2float(Z[o]));
        float zv = __half2float(Z[o + Dd]);
        float cc = zv * sigm(zv);
        h = f * h + (1.f - f) * cc;
        a *= f;
    }
    g_SA[id] = a;
    g_SB[id] = h;
}
__global__ void scan2_kernel(const __half* __restrict__ Z, const float* __restrict__ lbrow,
                             __half* __restrict__ H) {
    int id = blockIdx.x * blockDim.x + threadIdx.x;
    int d = id % Dd;
    int c = (id / Dd) % CH;
    int b = id / (Dd * CH);
    float l = lbrow[d];
    float h = 0.f;
    for (int j = 0; j < c; j++) {
        int sid = (b * CH + j) * Dd + d;
        h = g_SA[sid] * h + g_SB[sid];
    }
    size_t base = ((size_t)b * Tt + (size_t)c * TC) * (3 * Dd) + d;
    size_t hbase = ((size_t)b * Tt + (size_t)c * TC) * Dd + d;
    for (int t = 0; t < TC; t++) {
        size_t o = base + (size_t)t * (3 * Dd);
        float f  = l + (1.f - l) * sigm(__half2float(Z[o]));
        float zv = __half2float(Z[o + Dd]);
        float cc = zv * sigm(zv);
        h = f * h + (1.f - f) * cc;
        H[hbase + (size_t)t * Dd] = __float2half_rn(h);
    }
}

// ---------------- fused: rz = rms(ZG); s = xg*h*sig(h); S = half(s*wgo); rB --
__global__ void s_fused_kernel(const __half* __restrict__ Z, const float* __restrict__ wnorm,
                               const __half* __restrict__ H, const float* __restrict__ wgo,
                               __half* __restrict__ S, float* __restrict__ rs_out) {
    __shared__ float zbuf[Dd];
    int n = blockIdx.x;
    const __half* zg = Z + (size_t)n * (3 * Dd) + 2 * Dd;
    float s1 = 0.f;
    for (int d = threadIdx.x; d < Dd; d += 256) {
        float v = __half2float(zg[d]);
        zbuf[d] = v;
        s1 += v * v;
    }
    float rz = rsqrtf(blockReduce1(s1) / Dd + EPSf);
    float s2 = 0.f;
    for (int d = threadIdx.x; d < Dd; d += 256) {
        size_t o = (size_t)n * Dd + d;
        float xg = zbuf[d] * rz * wnorm[d];
        float h  = __half2float(H[o]);
        float s  = xg * h * sigm(h);
        S[o] = __float2half_rn(s * wgo[d]);
        s2 += s * s;
    }
    s2 = blockReduce1(s2);
    if (threadIdx.x == 0) rs_out[n] = rsqrtf(s2 / Dd + EPSf);
}

// ---------------- launcher ----------------------------------------------------
extern "C" void kernel_launch(void* const* d_in, const int* in_sizes, int n_in,
                              void* d_out, int out_size) {
    const int*   x       = (const int*)  d_in[0];
    const float* emb     = (const float*)d_in[1];
    const float* wg_in   = (const float*)d_in[2];
    const float* wg_f    = (const float*)d_in[3];
    const float* wg_c    = (const float*)d_in[4];
    const float* wg_g    = (const float*)d_in[5];
    const float* wg_norm = (const float*)d_in[6];
    const float* lf_w    = (const float*)d_in[7];
    const float* lf_b    = (const float*)d_in[8];
    const float* lc_w    = (const float*)d_in[9];
    const float* lc_b    = (const float*)d_in[10];
    const float* lg_w    = (const float*)d_in[11];
    const float* lg_b    = (const float*)d_in[12];
    const float* weight_l= (const float*)d_in[13];
    const float* wg_o    = (const float*)d_in[14];
    const float* lo_w    = (const float*)d_in[15];
    const float* lo_b    = (const float*)d_in[16];
    const float* glu_wg  = (const float*)d_in[17];
    const float* glu_wgo = (const float*)d_in[18];
    const float* glu_wd  = (const float*)d_in[19];
    const float* lu_w    = (const float*)d_in[20];
    const float* lu_b    = (const float*)d_in[21];
    const float* ln_w    = (const float*)d_in[22];
    const float* ln_b    = (const float*)d_in[23];
    const float* out_w   = (const float*)d_in[24];
    const float* out_b   = (const float*)d_in[25];
    float* out = (float*)d_out;

    float *pY, *pXO, *pB3, *pBLU, *pGS, *prA, *prB, *pLB;
    __half *pYT, *pZ, *pH, *pS, *pXS, *pGP, *pWS;
    cudaGetSymbolAddress((void**)&pY,  g_Y);
    cudaGetSymbolAddress((void**)&pYT, g_YT);
    cudaGetSymbolAddress((void**)&pZ,  g_Z);
    cudaGetSymbolAddress((void**)&pH,  g_H);
    cudaGetSymbolAddress((void**)&pS,  g_S);
    cudaGetSymbolAddress((void**)&pXO, g_XO);
    cudaGetSymbolAddress((void**)&pXS, g_XS);
    cudaGetSymbolAddress((void**)&pGP, g_GP);
    cudaGetSymbolAddress((void**)&pWS, g_WS);
    cudaGetSymbolAddress((void**)&pGS, g_GS);
    cudaGetSymbolAddress((void**)&pB3, g_B3);
    cudaGetSymbolAddress((void**)&pBLU, g_BLU);
    cudaGetSymbolAddress((void**)&prA, g_rA);
    cudaGetSymbolAddress((void**)&prB, g_rB);
    cudaGetSymbolAddress((void**)&pLB, g_LB);

    cudaFuncSetAttribute(tc_gemm<false,false>, cudaFuncAttributeMaxDynamicSharedMemorySize, GEMM_SMEM_BYTES);
    cudaFuncSetAttribute(tc_gemm<true,false>,  cudaFuncAttributeMaxDynamicSharedMemorySize, GEMM_SMEM_BYTES);
    cudaFuncSetAttribute(tc_gemm<false,true>,  cudaFuncAttributeMaxDynamicSharedMemorySize, GEMM_SMEM_BYTES);

    lb_kernel<<<NBk, 256>>>(weight_l);
    embed_kernel<<<(NN * Dd / 4) / 256, 256>>>(x, emb);

    dim3 gFCG(3 * Dd / 128, NN / 128);
    dim3 gD(Dd / 128, NN / 128);
    dim3 gU(2 * Ii / 128, NN / 128);      // 44 x 64
    dim3 gV(Vv / 128, NN / 128);
    const int scanBlocks = (Bb * CH * Dd) / 256;
    const int tD = DDe / 4;
    const int tU2 = 2 * IDe / 4;
    const int tN = IDe / 4;

    for (int i = 0; i < NBk; i++) {
        const float* wgn  = wg_norm + i * Dd;
        const float* wgo  = wg_o    + i * Dd;
        const float* gwg  = glu_wg  + i * Dd;
        const float* gwgo = glu_wgo + i * Dd;
        const float* gwd  = glu_wd  + i * Ii;

        bias3_kernel<<<(3 * Dd) / 256, 256>>>(lf_b + i*Dd, lc_b + i*Dd, lg_b + i*Dd);
        rms_rows_kernel<<<NN, 256>>>(pY, wg_in + i*Dd, prA, Dd);
        wscale3_kernel<<<(3 * tD + 255) / 256, 256>>>(
            (const float4*)(lf_w + (size_t)i*DDe), (const float4*)(lc_w + (size_t)i*DDe),
            (const float4*)(lg_w + (size_t)i*DDe),
            wg_in + i*Dd, wg_f + i*Dd, wg_c + i*Dd, wg_g + i*Dd, (__half2*)pWS);
        // merged f/c/g GEMM -> Z (fp16) = [NN][ZF|ZC|ZG]
        tc_gemm<true,false><<<gFCG, 128, GEMM_SMEM_BYTES>>>(3 * Dd, Dd, pYT, pWS, prA, pB3,
                                                nullptr, pZ, nullptr, nullptr, nullptr, nullptr);

        // gated recurrence over t: 2-pass chunked scan
        scan1_kernel<<<scanBlocks, 256>>>(pZ, pLB + i * Dd);
        scan2_kernel<<<scanBlocks, 256>>>(pZ, pLB + i * Dd, pH);

        // fused: x_g row-rms + s = x_g*h*sig(h), S = half(s*wgo)
        s_fused_kernel<<<NN, 256>>>(pZ, wgn, pH, wgo, pS, prB);

        // x_o = y + rms(s, wg_o) @ lo_w^T + lo_b ; also XS = half(XO*gwg*gwgo)
        wcvt_kernel<<<(tD + 255) / 256, 256>>>((const float4*)(lo_w + (size_t)i*DDe), (__half2*)pWS, tD);
        tc_gemm<false,false><<<gD, 128, GEMM_SMEM_BYTES>>>(Dd, Dd, pS, pWS, prB, lo_b + i*Dd,
                                                pY, pXO, pXS, gwg, gwgo, nullptr);

        // GLU up-proj row scale; fused lu GEMM with in-epilogue GLU gate
        rms_rows_kernel<<<NN, 256>>>(pXO, gwg, prA, Dd);
        wperm_lu_kernel<<<(tU2 + 255) / 256, 256>>>((const float4*)(lu_w + (size_t)i*2*IDe), (__half2*)pWS);
        biasperm_lu_kernel<<<(2 * Ii) / 256, 256>>>(lu_b + (size_t)i*2*Ii);
        tc_gemm<false,true><<<gU, 128, GEMM_SMEM_BYTES>>>(2 * Ii, Dd, pXS, pWS, prA, pBLU,
                                                nullptr, nullptr, pGP, gwd, nullptr, pGS);
        glu_rms_kernel<<<(NN + 255) / 256, 256>>>(pGS, prB);

        // y_next = x_o + rms(gp, glu_wd) @ ln_w^T + ln_b ; also YT = half(y_next)
        wcvt_kernel<<<(tN + 255) / 256, 256>>>((const float4*)(ln_w + (size_t)i*IDe), (__half2*)pWS, tN);
        tc_gemm<false,false><<<gD, 128, GEMM_SMEM_BYTES>>>(Dd, Ii, pGP, pWS, prB, ln_b + i*Dd,
                                                pXO, pY, pYT, nullptr, nullptr, nullptr);
    }

    // logits = yt @ half(out_w)^T + out_b  -> [B,T,V]
    wcvt_kernel<<<(Vv * Dd / 4 + 255) / 256, 256>>>((const float4*)out_w, (__half2*)pWS, Vv * Dd / 4);
    tc_gemm<false,false><<<gV, 128, GEMM_SMEM_BYTES>>>(Vv, Dd, pYT, pWS, nullptr, out_b,
                                                nullptr, out, nullptr, nullptr, nullptr, nullptr);
}